// round 12
// baseline (speedup 1.0000x reference)
#include <cuda_runtime.h>

// ContradictionMonitor — GB300 sm_103a, round 12
// R5 structure (35.3us baseline) + L2 prefetch (j+2) to shorten LDG latency.
// B=8, T=4096, D=1024, A=32, S=16, TTL=64 -> H=256, W=241
#define NB 8
#define NT 4096
#define ND 1024
#define ND4 (ND / 4)
#define NA 32
#define NS 16
#define NH 256
#define NW (NH - NS + 1)
#define NTHR 256
#define NWARP (NTHR / 32)
#define BA (NB * NA)
#define VOCAB 64

#define CH 4              // row chunks per anchor
#define RPC (NH / CH)     // 64 rows per chunk-CTA
#define RPW (RPC / NWARP) // 8 rows per warp
#define NJ 8              // d-chunks of 128 floats

#define MK(x) (1ULL << (x))
#define FULLM 0xffffffffu

__device__ float g_acc[CH][BA][ND];   // per-chunk per-d partial sums (4 MB)
__device__ float g_shift[CH][BA];     // per-chunk sum of row norms
__device__ int   g_cnt[BA];           // arrival counters (zero-init, self-resetting)

__constant__ int c_alias[VOCAB] = {
    -1, -1, -1, -1, -1, -1, -1, -1, -1, -1,
    -1, 11, -1, 11, -1, -1, 11, -1, -1, -1,
    -1, 21, 21, 21, -1, -1, -1, -1, -1, -1,
    -1, 31, 31, 31, -1, -1, -1, -1, -1, -1,
    -1, 41, 41, 41, 41, -1, -1, -1, -1, -1,
    -1, 51, 51, 51, -1, -1, -1, -1, -1, -1,
    -1, -1, -1, -1
};

__constant__ unsigned long long c_cmask[VOCAB] = {
    0, 0, 0, 0, 0, 0, 0, 0, 0, 0,
    0, MK(11) | MK(13) | MK(16), 0, 0, 0, 0, 0, 0, 0, 0,
    0, MK(14) | MK(15) | MK(21) | MK(22) | MK(23), 0, 0, 0, 0, 0, 0, 0, 0,
    0, MK(15) | MK(31) | MK(32) | MK(33), 0, 0, 0, 0, 0, 0, 0, 0,
    0, MK(41) | MK(42) | MK(43) | MK(44), 0, 0, 0, 0, 0, 0, 0, 0,
    0, MK(15) | MK(51) | MK(52) | MK(53), 0, 0, 0, 0, 0, 0, 0, 0,
    0, 0, 0, 0
};

__device__ __forceinline__ void pf_l2(const void* p) {
    asm volatile("prefetch.global.L2 [%0];" :: "l"(p));
}

__global__ __launch_bounds__(NTHR, 4)
void cm_fused(const float* __restrict__ hidden,
              const float* __restrict__ anchor_repr,
              const int* __restrict__ input_ids,
              const int* __restrict__ anchor_end,
              float* __restrict__ out) {
    __shared__ float sacc[NWARP][ND];   // 32 KB per-warp mean partials
    __shared__ float anc_s[ND];         // 4 KB (kept live into finalize)
    __shared__ float sqp[RPC];
    __shared__ float red[NWARP];
    __shared__ int   ftok[NH];
    __shared__ int   sspan[NS];
    __shared__ int   salias[VOCAB];
    __shared__ float wred[NWARP][9];
    __shared__ int   slast;

    const int tid = threadIdx.x;
    const int lane = tid & 31;
    const int w = tid >> 5;
    const int aid = blockIdx.x >> 2;   // anchor id 0..255
    const int c = blockIdx.x & 3;      // chunk
    const int b = aid >> 5;            // batch

    const int ae = anchor_end[aid];
    const int start = ae + 1 + c * RPC;

    // stage anchor
    reinterpret_cast<float4*>(anc_s)[tid] =
        reinterpret_cast<const float4*>(anchor_repr)[aid * ND4 + tid];

    // warp w owns rows [w*RPW, w*RPW+RPW) of this chunk
    const float* base = hidden + (size_t)b * NT * ND + (size_t)(start + w * RPW) * ND;
    const float* lanep = base + lane * 4;

    // prefetch chunk j=1 before entering the loop (j=0 loads go straight to LDG)
#pragma unroll
    for (int r = 0; r < RPW; r++)
        pf_l2(lanep + (size_t)r * ND + 128);

    __syncthreads();

    float sq[RPW];
#pragma unroll
    for (int r = 0; r < RPW; r++) sq[r] = 0.f;

#pragma unroll 1
    for (int j = 0; j < NJ; j++) {
        const int off = j * 128 + lane * 4;
        float4 x[RPW];
#pragma unroll
        for (int r = 0; r < RPW; r++)
            x[r] = *reinterpret_cast<const float4*>(lanep + (size_t)r * ND + j * 128);

        // prefetch chunk j+2 into L2 while j's loads are in flight
        if (j + 2 < NJ) {
#pragma unroll
            for (int r = 0; r < RPW; r++)
                pf_l2(lanep + (size_t)r * ND + (j + 2) * 128);
        }

        const float4 anc4 = *reinterpret_cast<const float4*>(anc_s + off);
        float4 accj = make_float4(0.f, 0.f, 0.f, 0.f);
#pragma unroll
        for (int r = 0; r < RPW; r++) {
            float4 v = x[r];
            accj.x += v.x; accj.y += v.y; accj.z += v.z; accj.w += v.w;
            float dx = v.x - anc4.x, dy = v.y - anc4.y;
            float dz = v.z - anc4.z, dw = v.w - anc4.w;
            sq[r] += dx * dx + dy * dy + dz * dz + dw * dw;
        }
        *reinterpret_cast<float4*>(&sacc[w][off]) = accj;
    }

    // interleaved 8-chain butterfly for per-row squared sums
#pragma unroll
    for (int o = 16; o > 0; o >>= 1) {
#pragma unroll
        for (int r = 0; r < RPW; r++)
            sq[r] += __shfl_xor_sync(FULLM, sq[r], o);
    }
#pragma unroll
    for (int r = 0; r < RPW; r++)
        if (lane == r) sqp[w * RPW + r] = sq[r];
    __syncthreads();

    // cross-warp mean reduce: thread tid owns float4 column tid
    float4 tot = make_float4(0.f, 0.f, 0.f, 0.f);
#pragma unroll
    for (int ww = 0; ww < NWARP; ww++) {
        float4 p = reinterpret_cast<float4*>(sacc[ww])[tid];
        tot.x += p.x; tot.y += p.y; tot.z += p.z; tot.w += p.w;
    }
    reinterpret_cast<float4*>(g_acc[c][aid])[tid] = tot;

    // shift: per-row norms -> chunk sum
    float sh = (tid < RPC) ? sqrtf(sqp[tid]) : 0.f;
#pragma unroll
    for (int o = 16; o > 0; o >>= 1)
        sh += __shfl_xor_sync(FULLM, sh, o);
    if (lane == 0) red[w] = sh;
    __syncthreads();
    if (tid == 0) {
        float s = 0.f;
#pragma unroll
        for (int ww = 0; ww < NWARP; ww++) s += red[ww];
        g_shift[c][aid] = s;
    }

    // ---- last-CTA election ----
    __threadfence();
    __syncthreads();
    if (tid == 0)
        slast = (atomicAdd(&g_cnt[aid], 1) == CH - 1) ? 1 : 0;
    __syncthreads();
    if (!slast) return;

    // =========== finalize (runs on exactly one CTA per anchor) ===========
    const int start0 = ae + 1;
    ftok[tid] = input_ids[b * NT + start0 + tid];
    if (tid < NS) sspan[tid] = input_ids[b * NT + ae - NS + 1 + tid];
    if (tid < VOCAB) salias[tid] = c_alias[tid];
    if (tid == 0) g_cnt[aid] = 0;   // reset for next launch / replay

    // combine chunk partials -> mean_future, sim inputs
    float4 m4 = make_float4(0.f, 0.f, 0.f, 0.f);
#pragma unroll
    for (int cc = 0; cc < CH; cc++) {
        float4 p = reinterpret_cast<const float4*>(g_acc[cc][aid])[tid];
        m4.x += p.x; m4.y += p.y; m4.z += p.z; m4.w += p.w;
    }
    const float inv_h = 1.0f / NH;
    m4.x *= inv_h; m4.y *= inv_h; m4.z *= inv_h; m4.w *= inv_h;
    const float4 anc = reinterpret_cast<const float4*>(anc_s)[tid];

    float dotp = m4.x * anc.x + m4.y * anc.y + m4.z * anc.z + m4.w * anc.w;
    float nf2 = m4.x * m4.x + m4.y * m4.y + m4.z * m4.z + m4.w * m4.w;
    float nr2 = anc.x * anc.x + anc.y * anc.y + anc.z * anc.z + anc.w * anc.w;

    __syncthreads();  // ftok/sspan/salias ready

    const int anchor_tok = sspan[NS - 1];
    float eqa = (ftok[tid] == anchor_tok) ? 1.0f : 0.0f;

    // span analysis via warp intrinsics (every warp redundantly)
    const int s16 = lane & 15;
    const int sps = sspan[s16];
    const unsigned ml = __match_any_sync(FULLM, sps) & 0xffffu;
    const int count = __popc(ml);
    const bool first = (ml & ((1u << s16) - 1u)) == 0u;
    const unsigned FO = __ballot_sync(FULLM, first) & 0xffffu;
    const float denom = (float)__popc(FO);
    const int maxc = __reduce_max_sync(FULLM, count);
    const int modev = (count == maxc) ? sps : VOCAB;
    const int mode = __reduce_min_sync(FULLM, modev);
    const int al = salias[sps];
    const unsigned hasmask = __ballot_sync(FULLM, al >= 0) & 0xffffu;
    const int fi = hasmask ? (__ffs(hasmask) - 1) : 0;
    const int firstRoot = __shfl_sync(FULLM, al, fi);
    const int root = hasmask ? firstRoot : mode;
    const unsigned long long rmask = c_cmask[root];
    const bool hasT = (rmask != 0ULL);

    // per-window metrics (thread tid -> window tid, tid < 241)
    float v_sims = 0.f, v_best = -1e30f, v_rp = 0.f, v_reg = 0.f, v_cnt = 0.f;
    if (tid < NW) {
        unsigned long long pm = 0ULL;
        int exact_i = 0, rp_i = 0, ac_i = 0, hd_i = 0;
        float positional = 0.f;
#pragma unroll
        for (int s = 0; s < NS; s++) {
            const int tk = ftok[tid + s];
            pm |= (1ULL << tk);
            const int e = (tk == sspan[s]) ? 1 : 0;
            exact_i += e;
            positional += (float)e * ((1.0f - 0.04f * (float)s) * (1.0f / 11.2f));
            rp_i += (tk == root) ? 1 : 0;
            ac_i += (salias[tk] == root) ? 1 : 0;
            hd_i += (int)((rmask >> tk) & 1ULL);
        }
        int ov_i = 0;
#pragma unroll
        for (int s = 0; s < NS; s++)
            ov_i += (int)((FO >> s) & 1u) & (int)((pm >> sspan[s]) & 1ULL);
        const float invs = 1.0f / NS;
        const float exact = (float)exact_i * invs;
        const float rp = (float)rp_i * invs;
        const float ac = (float)ac_i * invs;
        const float hd = (float)hd_i * invs;
        const float ov = (float)ov_i / denom;
        const float regime = hasT ? (0.55f * hd + 0.2f * ov + 0.15f * ac + 0.1f * rp)
                                  : (0.45f * exact + 0.3f * ov + 0.1f * ac + 0.15f * rp);
        const float sims = 0.25f * exact + 0.15f * ov + 0.35f * positional + 0.25f * regime;
        v_sims = sims;
        v_best = sims;
        v_rp = rp;
        v_reg = regime;
        v_cnt = (sims >= 0.6f) ? 1.0f : 0.0f;
    }

    // single combined block reduction: 8 sums + 1 max
    float r0 = dotp, r1 = nf2, r2 = nr2, r3 = eqa;
    float r4 = v_sims, r5 = v_rp, r6 = v_reg, r7 = v_cnt, r8 = v_best;
#pragma unroll
    for (int o = 16; o > 0; o >>= 1) {
        r0 += __shfl_xor_sync(FULLM, r0, o);
        r1 += __shfl_xor_sync(FULLM, r1, o);
        r2 += __shfl_xor_sync(FULLM, r2, o);
        r3 += __shfl_xor_sync(FULLM, r3, o);
        r4 += __shfl_xor_sync(FULLM, r4, o);
        r5 += __shfl_xor_sync(FULLM, r5, o);
        r6 += __shfl_xor_sync(FULLM, r6, o);
        r7 += __shfl_xor_sync(FULLM, r7, o);
        r8 = fmaxf(r8, __shfl_xor_sync(FULLM, r8, o));
    }
    if (lane == 0) {
        wred[w][0] = r0; wred[w][1] = r1; wred[w][2] = r2; wred[w][3] = r3;
        wred[w][4] = r4; wred[w][5] = r5; wred[w][6] = r6; wred[w][7] = r7;
        wred[w][8] = r8;
    }
    __syncthreads();

    if (tid == 0) {
        float s0 = 0, s1 = 0, s2 = 0, s3 = 0, s4 = 0, s5 = 0, s6 = 0, s7 = 0;
        float s8 = -1e30f;
#pragma unroll
        for (int ww = 0; ww < NWARP; ww++) {
            s0 += wred[ww][0]; s1 += wred[ww][1]; s2 += wred[ww][2]; s3 += wred[ww][3];
            s4 += wred[ww][4]; s5 += wred[ww][5]; s6 += wred[ww][6]; s7 += wred[ww][7];
            s8 = fmaxf(s8, wred[ww][8]);
        }
        const float nrr = fmaxf(sqrtf(s2), 1e-8f);
        const float nff = fmaxf(sqrtf(s1), 1e-8f);
        const float sim = s0 / (nrr * nff);
        const float hidden_c = fmaxf(0.0f, (1.0f - sim) * 0.5f);
        const float token_c = 1.0f - s3 * (1.0f / NH);

        float shsum = 0.f;
#pragma unroll
        for (int cc = 0; cc < CH; cc++) shsum += g_shift[cc][aid];
        const float future_shift = shsum * (1.0f / NH);

        const float invw = 1.0f / (float)NW;
        const float mrp = s5 * invw;
        const float mrc = s6 * invw;
        const float dmass = s7 * invw;
        const float dcoh = 0.6f * (s4 * invw) + 0.25f * mrp + 0.15f * mrc;
        const float pattern_c = 1.0f - (0.6f * s8 + 0.2f * mrp + 0.2f * mrc);
        float contr = 0.2f * hidden_c + 0.2f * token_c + 0.6f * pattern_c;
        contr = fminf(fmaxf(contr, 0.0f), 1.0f);

        out[0 * BA + aid] = contr;
        out[1 * BA + aid] = future_shift;
        out[2 * BA + aid] = sim;
        out[3 * BA + aid] = hidden_c;
        out[4 * BA + aid] = token_c;
        out[5 * BA + aid] = pattern_c;
        out[6 * BA + aid] = dmass;
        out[7 * BA + aid] = dcoh;
    }
}

extern "C" void kernel_launch(void* const* d_in, const int* in_sizes, int n_in,
                              void* d_out, int out_size) {
    const float* hidden = (const float*)d_in[0];
    const float* anchor_repr = (const float*)d_in[1];
    const int* input_ids = (const int*)d_in[2];
    const int* anchor_end = (const int*)d_in[3];
    (void)in_sizes; (void)n_in; (void)out_size;
    cm_fused<<<BA * CH, NTHR>>>(hidden, anchor_repr, input_ids, anchor_end, (float*)d_out);
}

// round 13
// speedup vs baseline: 1.1469x; 1.1469x over previous
#include <cuda_runtime.h>

// ContradictionMonitor — GB300 sm_103a, round 13
// R5 streaming core + chunk-major scheduling; token phase on c0 (off the tail),
// slim last-arriver finalize.
// B=8, T=4096, D=1024, A=32, S=16, TTL=64 -> H=256, W=241
#define NB 8
#define NT 4096
#define ND 1024
#define ND4 (ND / 4)
#define NA 32
#define NS 16
#define NH 256
#define NW (NH - NS + 1)
#define NTHR 256
#define NWARP (NTHR / 32)
#define BA (NB * NA)
#define VOCAB 64

#define CH 4              // row chunks per anchor
#define RPC (NH / CH)     // 64 rows per chunk-CTA
#define RPW (RPC / NWARP) // 8 rows per warp
#define NJ 8              // d-chunks of 128 floats

#define MK(x) (1ULL << (x))
#define FULLM 0xffffffffu

__device__ float g_acc[CH][BA][ND];   // per-chunk per-d partial sums (4 MB)
__device__ float g_shift[CH][BA];     // per-chunk sum of row norms
__device__ float g_tokc[BA];          // stash: token_c (written by c0)
__device__ float g_patc[BA];          // stash: pattern_c (written by c0)
__device__ int   g_cnt[BA];           // arrival counters (zero-init, self-resetting)

__constant__ int c_alias[VOCAB] = {
    -1, -1, -1, -1, -1, -1, -1, -1, -1, -1,
    -1, 11, -1, 11, -1, -1, 11, -1, -1, -1,
    -1, 21, 21, 21, -1, -1, -1, -1, -1, -1,
    -1, 31, 31, 31, -1, -1, -1, -1, -1, -1,
    -1, 41, 41, 41, 41, -1, -1, -1, -1, -1,
    -1, 51, 51, 51, -1, -1, -1, -1, -1, -1,
    -1, -1, -1, -1
};

__constant__ unsigned long long c_cmask[VOCAB] = {
    0, 0, 0, 0, 0, 0, 0, 0, 0, 0,
    0, MK(11) | MK(13) | MK(16), 0, 0, 0, 0, 0, 0, 0, 0,
    0, MK(14) | MK(15) | MK(21) | MK(22) | MK(23), 0, 0, 0, 0, 0, 0, 0, 0,
    0, MK(15) | MK(31) | MK(32) | MK(33), 0, 0, 0, 0, 0, 0, 0, 0,
    0, MK(41) | MK(42) | MK(43) | MK(44), 0, 0, 0, 0, 0, 0, 0, 0,
    0, MK(15) | MK(51) | MK(52) | MK(53), 0, 0, 0, 0, 0, 0, 0, 0,
    0, 0, 0, 0
};

__global__ __launch_bounds__(NTHR, 4)
void cm_fused(const float* __restrict__ hidden,
              const float* __restrict__ anchor_repr,
              const int* __restrict__ input_ids,
              const int* __restrict__ anchor_end,
              float* __restrict__ out) {
    __shared__ float sacc[NWARP][ND];   // 32 KB per-warp mean partials
    __shared__ float anc_s[ND];         // 4 KB (kept live into finalize)
    __shared__ float sqp[RPC];
    __shared__ float red[NWARP];
    __shared__ int   ftok[NH];
    __shared__ int   sspan[NS];
    __shared__ int   salias[VOCAB];
    __shared__ float wred[NWARP][6];
    __shared__ int   slast;

    const int tid = threadIdx.x;
    const int lane = tid & 31;
    const int w = tid >> 5;
    const int aid = blockIdx.x & (BA - 1);   // chunk-major: anchor id
    const int c = blockIdx.x >> 8;           // chunk 0..3
    const int b = aid >> 5;                  // batch

    const int ae = anchor_end[aid];
    const int start = ae + 1 + c * RPC;

    // stage anchor
    reinterpret_cast<float4*>(anc_s)[tid] =
        reinterpret_cast<const float4*>(anchor_repr)[aid * ND4 + tid];
    __syncthreads();

    // ---- streaming: warp w owns rows [w*RPW, w*RPW+RPW) of this chunk ----
    const float* base = hidden + (size_t)b * NT * ND + (size_t)(start + w * RPW) * ND;

    float sq[RPW];
#pragma unroll
    for (int r = 0; r < RPW; r++) sq[r] = 0.f;

#pragma unroll 1
    for (int j = 0; j < NJ; j++) {
        const int off = j * 128 + lane * 4;
        float4 x[RPW];
#pragma unroll
        for (int r = 0; r < RPW; r++)
            x[r] = *reinterpret_cast<const float4*>(base + (size_t)r * ND + off);
        const float4 anc4 = *reinterpret_cast<const float4*>(anc_s + off);
        float4 accj = make_float4(0.f, 0.f, 0.f, 0.f);
#pragma unroll
        for (int r = 0; r < RPW; r++) {
            float4 v = x[r];
            accj.x += v.x; accj.y += v.y; accj.z += v.z; accj.w += v.w;
            float dx = v.x - anc4.x, dy = v.y - anc4.y;
            float dz = v.z - anc4.z, dw = v.w - anc4.w;
            sq[r] += dx * dx + dy * dy + dz * dz + dw * dw;
        }
        *reinterpret_cast<float4*>(&sacc[w][off]) = accj;
    }

    // interleaved 8-chain butterfly for per-row squared sums
#pragma unroll
    for (int o = 16; o > 0; o >>= 1) {
#pragma unroll
        for (int r = 0; r < RPW; r++)
            sq[r] += __shfl_xor_sync(FULLM, sq[r], o);
    }
#pragma unroll
    for (int r = 0; r < RPW; r++)
        if (lane == r) sqp[w * RPW + r] = sq[r];
    __syncthreads();

    // cross-warp mean reduce: thread tid owns float4 column tid
    float4 tot = make_float4(0.f, 0.f, 0.f, 0.f);
#pragma unroll
    for (int ww = 0; ww < NWARP; ww++) {
        float4 p = reinterpret_cast<float4*>(sacc[ww])[tid];
        tot.x += p.x; tot.y += p.y; tot.z += p.z; tot.w += p.w;
    }
    reinterpret_cast<float4*>(g_acc[c][aid])[tid] = tot;

    // shift: per-row norms -> chunk sum
    float sh = (tid < RPC) ? sqrtf(sqp[tid]) : 0.f;
#pragma unroll
    for (int o = 16; o > 0; o >>= 1)
        sh += __shfl_xor_sync(FULLM, sh, o);
    if (lane == 0) red[w] = sh;
    __syncthreads();
    if (tid == 0) {
        float s = 0.f;
#pragma unroll
        for (int ww = 0; ww < NWARP; ww++) s += red[ww];
        g_shift[c][aid] = s;
    }

    // ============ token phase on the c==0 CTA (off the anchor tail) ============
    if (c == 0) {
        const int start0 = ae + 1;
        ftok[tid] = input_ids[b * NT + start0 + tid];
        if (tid < NS) sspan[tid] = input_ids[b * NT + ae - NS + 1 + tid];
        if (tid < VOCAB) salias[tid] = c_alias[tid];
        __syncthreads();

        const int anchor_tok = sspan[NS - 1];
        float eqa = (ftok[tid] == anchor_tok) ? 1.0f : 0.0f;

        // span analysis via warp intrinsics (every warp redundantly)
        const int s16 = lane & 15;
        const int sps = sspan[s16];
        const unsigned ml = __match_any_sync(FULLM, sps) & 0xffffu;
        const int count = __popc(ml);
        const bool first = (ml & ((1u << s16) - 1u)) == 0u;
        const unsigned FO = __ballot_sync(FULLM, first) & 0xffffu;
        const float denom = (float)__popc(FO);
        const int maxc = __reduce_max_sync(FULLM, count);
        const int modev = (count == maxc) ? sps : VOCAB;
        const int mode = __reduce_min_sync(FULLM, modev);
        const int al = salias[sps];
        const unsigned hasmask = __ballot_sync(FULLM, al >= 0) & 0xffffu;
        const int fi = hasmask ? (__ffs(hasmask) - 1) : 0;
        const int firstRoot = __shfl_sync(FULLM, al, fi);
        const int root = hasmask ? firstRoot : mode;
        const unsigned long long rmask = c_cmask[root];
        const bool hasT = (rmask != 0ULL);

        float v_sims = 0.f, v_best = -1e30f, v_rp = 0.f, v_reg = 0.f, v_cnt = 0.f;
        if (tid < NW) {
            unsigned long long pm = 0ULL;
            int exact_i = 0, rp_i = 0, ac_i = 0, hd_i = 0;
            float positional = 0.f;
#pragma unroll
            for (int s = 0; s < NS; s++) {
                const int tk = ftok[tid + s];
                pm |= (1ULL << tk);
                const int e = (tk == sspan[s]) ? 1 : 0;
                exact_i += e;
                positional += (float)e * ((1.0f - 0.04f * (float)s) * (1.0f / 11.2f));
                rp_i += (tk == root) ? 1 : 0;
                ac_i += (salias[tk] == root) ? 1 : 0;
                hd_i += (int)((rmask >> tk) & 1ULL);
            }
            int ov_i = 0;
#pragma unroll
            for (int s = 0; s < NS; s++)
                ov_i += (int)((FO >> s) & 1u) & (int)((pm >> sspan[s]) & 1ULL);
            const float invs = 1.0f / NS;
            const float exact = (float)exact_i * invs;
            const float rp = (float)rp_i * invs;
            const float ac = (float)ac_i * invs;
            const float hd = (float)hd_i * invs;
            const float ov = (float)ov_i / denom;
            const float regime = hasT ? (0.55f * hd + 0.2f * ov + 0.15f * ac + 0.1f * rp)
                                      : (0.45f * exact + 0.3f * ov + 0.1f * ac + 0.15f * rp);
            const float sims = 0.25f * exact + 0.15f * ov + 0.35f * positional + 0.25f * regime;
            v_sims = sims;
            v_best = sims;
            v_rp = rp;
            v_reg = regime;
            v_cnt = (sims >= 0.6f) ? 1.0f : 0.0f;
        }

        // combined reduction: 5 sums + 1 max
        float r0 = eqa, r1 = v_sims, r2 = v_rp, r3 = v_reg, r4 = v_cnt, r5 = v_best;
#pragma unroll
        for (int o = 16; o > 0; o >>= 1) {
            r0 += __shfl_xor_sync(FULLM, r0, o);
            r1 += __shfl_xor_sync(FULLM, r1, o);
            r2 += __shfl_xor_sync(FULLM, r2, o);
            r3 += __shfl_xor_sync(FULLM, r3, o);
            r4 += __shfl_xor_sync(FULLM, r4, o);
            r5 = fmaxf(r5, __shfl_xor_sync(FULLM, r5, o));
        }
        if (lane == 0) {
            wred[w][0] = r0; wred[w][1] = r1; wred[w][2] = r2;
            wred[w][3] = r3; wred[w][4] = r4; wred[w][5] = r5;
        }
        __syncthreads();

        if (tid == 0) {
            float s0 = 0, s1 = 0, s2 = 0, s3 = 0, s4 = 0, s5 = -1e30f;
#pragma unroll
            for (int ww = 0; ww < NWARP; ww++) {
                s0 += wred[ww][0]; s1 += wred[ww][1]; s2 += wred[ww][2];
                s3 += wred[ww][3]; s4 += wred[ww][4];
                s5 = fmaxf(s5, wred[ww][5]);
            }
            const float token_c = 1.0f - s0 * (1.0f / NH);
            const float invw = 1.0f / (float)NW;
            const float mrp = s2 * invw;
            const float mrc = s3 * invw;
            const float dmass = s4 * invw;
            const float dcoh = 0.6f * (s1 * invw) + 0.25f * mrp + 0.15f * mrc;
            const float pattern_c = 1.0f - (0.6f * s5 + 0.2f * mrp + 0.2f * mrc);

            out[4 * BA + aid] = token_c;
            out[5 * BA + aid] = pattern_c;
            out[6 * BA + aid] = dmass;
            out[7 * BA + aid] = dcoh;
            g_tokc[aid] = token_c;
            g_patc[aid] = pattern_c;
        }
    }

    // ---- last-CTA election (c0 arrives only after its stash is written) ----
    __threadfence();
    __syncthreads();
    if (tid == 0)
        slast = (atomicAdd(&g_cnt[aid], 1) == CH - 1) ? 1 : 0;
    __syncthreads();
    if (!slast) return;

    // =========== slim finalize (one CTA per anchor) ===========
    if (tid == 0) g_cnt[aid] = 0;   // reset for replay

    float4 m4 = make_float4(0.f, 0.f, 0.f, 0.f);
#pragma unroll
    for (int cc = 0; cc < CH; cc++) {
        float4 p = reinterpret_cast<const float4*>(g_acc[cc][aid])[tid];
        m4.x += p.x; m4.y += p.y; m4.z += p.z; m4.w += p.w;
    }
    const float inv_h = 1.0f / NH;
    m4.x *= inv_h; m4.y *= inv_h; m4.z *= inv_h; m4.w *= inv_h;
    const float4 anc = reinterpret_cast<const float4*>(anc_s)[tid];

    float r0 = m4.x * anc.x + m4.y * anc.y + m4.z * anc.z + m4.w * anc.w;
    float r1 = m4.x * m4.x + m4.y * m4.y + m4.z * m4.z + m4.w * m4.w;
    float r2 = anc.x * anc.x + anc.y * anc.y + anc.z * anc.z + anc.w * anc.w;
#pragma unroll
    for (int o = 16; o > 0; o >>= 1) {
        r0 += __shfl_xor_sync(FULLM, r0, o);
        r1 += __shfl_xor_sync(FULLM, r1, o);
        r2 += __shfl_xor_sync(FULLM, r2, o);
    }
    __syncthreads();   // wred reuse safe (c0 path may have used it)
    if (lane == 0) {
        wred[w][0] = r0; wred[w][1] = r1; wred[w][2] = r2;
    }
    __syncthreads();

    if (tid == 0) {
        float s0 = 0, s1 = 0, s2 = 0;
#pragma unroll
        for (int ww = 0; ww < NWARP; ww++) {
            s0 += wred[ww][0]; s1 += wred[ww][1]; s2 += wred[ww][2];
        }
        const float nrr = fmaxf(sqrtf(s2), 1e-8f);
        const float nff = fmaxf(sqrtf(s1), 1e-8f);
        const float sim = s0 / (nrr * nff);
        const float hidden_c = fmaxf(0.0f, (1.0f - sim) * 0.5f);

        float shsum = 0.f;
#pragma unroll
        for (int cc = 0; cc < CH; cc++) shsum += g_shift[cc][aid];
        const float future_shift = shsum * (1.0f / NH);

        const float token_c = g_tokc[aid];
        const float pattern_c = g_patc[aid];
        float contr = 0.2f * hidden_c + 0.2f * token_c + 0.6f * pattern_c;
        contr = fminf(fmaxf(contr, 0.0f), 1.0f);

        out[0 * BA + aid] = contr;
        out[1 * BA + aid] = future_shift;
        out[2 * BA + aid] = sim;
        out[3 * BA + aid] = hidden_c;
    }
}

extern "C" void kernel_launch(void* const* d_in, const int* in_sizes, int n_in,
                              void* d_out, int out_size) {
    const float* hidden = (const float*)d_in[0];
    const float* anchor_repr = (const float*)d_in[1];
    const int* input_ids = (const int*)d_in[2];
    const int* anchor_end = (const int*)d_in[3];
    (void)in_sizes; (void)n_in; (void)out_size;
    cm_fused<<<BA * CH, NTHR>>>(hidden, anchor_repr, input_ids, anchor_end, (float*)d_out);
}